// round 12
// baseline (speedup 1.0000x reference)
#include <cuda_runtime.h>
#include <math.h>

// S4D kernel generation:
//   K[h,l] = 2 * Re( sum_n C_scaled[h,n] * exp(dtA[h,n] * l) )
// Main loop: second-order real recurrence x(l+s) = a*x(l) - b*x(l-s)
//   (2 packed fma-ops per mode-pair per step), lane-split (l, mode-half),
//   shfl.bfly(1) combine, ping-pong state buffers.
// R12: constants (a, -b) live in REGISTERS (32 regs) -- the loop has zero
//   LDS. State 32 regs + consts 32 regs ~ 80 total. SEGS=4 -> grid 2048,
//   13.8 blocks/SM single wave under launch_bounds(32,14) (budget 146).
//   Lane-parallel init (R11) kept; constants staged via smem once.

#define NHALF_C 32
#define NPAIR   8      // f32x2 pairs per thread (16 modes; buddy lane has rest)
#define SEGS    4
#define LSTEP   16     // l advance per iteration (16 l per warp-iter)

typedef unsigned long long u64;

#define F2MUL(d,a,b)    asm("mul.rn.f32x2 %0, %1, %2;"     : "=l"(d) : "l"(a), "l"(b))
#define F2FMA(d,a,b,c)  asm("fma.rn.f32x2 %0, %1, %2, %3;" : "=l"(d) : "l"(a), "l"(b), "l"(c))
#define F2ADD(d,a,b)    asm("add.rn.f32x2 %0, %1, %2;"     : "=l"(d) : "l"(a), "l"(b))
#define F2PACK(d,lo,hi) asm("mov.b64 %0, {%1, %2};"        : "=l"(d) : "f"(lo), "f"(hi))
#define F2UNPK(lo,hi,s) asm("mov.b64 {%0, %1}, %2;"        : "=f"(lo), "=f"(hi) : "l"(s))

// Range-reduce x (double) into [-pi, pi], return float residue.
__device__ __forceinline__ float red2pi(double x) {
    const double TWO_PI     = 6.283185307179586476925286766559;
    const double INV_TWO_PI = 0.15915494309189533576888376337251;
    double k = rint(x * INV_TWO_PI);
    return (float)__fma_rn(k, -TWO_PI, x);
}

// Float Cody-Waite reduce: |s| <= ~160 -> [-pi, pi].
__device__ __forceinline__ float red2pi_f(float s) {
    const float INV2PI  = 0.15915494309189533f;
    const float PI2_HI  = 6.28125f;
    const float PI2_MID = 1.9353071786565706e-3f;   // 2*pi - 6.28125
    float k = rintf(s * INV2PI);
    float r = __fmaf_rn(k, -PI2_HI, s);
    return __fmaf_rn(k, -PI2_MID, r);
}

// One recurrence step + output; constants from register arrays au/nbu.
#define BODY(cur, old)                                                     \
    do {                                                                   \
        u64 t0, t1, t2, t3;                                                \
        F2ADD(t0, cur[0], cur[1]);                                         \
        F2ADD(t1, cur[2], cur[3]);                                         \
        F2ADD(t2, cur[4], cur[5]);                                         \
        F2ADD(t3, cur[6], cur[7]);                                         \
        F2ADD(t0, t0, t1);                                                 \
        F2ADD(t2, t2, t3);                                                 \
        F2ADD(t0, t0, t2);                                                 \
        float ra, rb; F2UNPK(ra, rb, t0);                                  \
        const float part = ra + rb;                                        \
        const float tot = part + __shfl_xor_sync(0xffffffffu, part, 1);    \
        _Pragma("unroll")                                                  \
        for (int p = 0; p < NPAIR; ++p) {                                  \
            u64 m0;                                                        \
            F2MUL(m0, old[p], nbu[p]);          /* -b*x(l-s) */            \
            F2FMA(old[p], cur[p], au[p], m0);   /* a*x(l) - b*x(l-s) */    \
        }                                                                  \
        if (half == 0) *out = tot;              /* 16 lanes, 64B store */  \
        out += LSTEP;                                                      \
    } while (0)

__global__ void __launch_bounds__(32, 14)
s4d_kernel(const float* __restrict__ C,
           const float* __restrict__ log_dt,
           const float* __restrict__ log_A_real,
           const float* __restrict__ A_imag,
           float* __restrict__ K,
           int H, int L, int iters)
{
    // staging (init only): per mode n
    __shared__ __align__(16) float4 stA[NHALF_C];   // {csr, csi, dre, dim}
    __shared__ __align__(16) float4 stB[NHALF_C];   // {phase_base, wr, wi, invb}
    __shared__ __align__(8)  float2 stC[NHALF_C];   // {a, -b}

    const int blk   = blockIdx.x;
    const int h     = blk / SEGS;
    const int seg   = blk % SEGS;
    const int lane  = threadIdx.x;
    const int lhalf = lane >> 1;     // which l within the 16-wide group
    const int half  = lane & 1;      // which 16-mode half this lane owns

    const int seg_len = L / SEGS;
    const int l_base  = seg * seg_len;
    const int l0      = l_base + lhalf;

    // dt via double exp (once) so --use_fast_math can't degrade it.
    const float dt = (float)exp((double)log_dt[h]);

    // ---------- Phase A: lane n computes mode n's invariants ----------
    {
        const int n   = lane;
        const int idx = h * NHALF_C + n;
        const float arl = log_A_real[idx];
        const float aim = A_imag[idx];
        const float c0  = C[2 * idx + 0];
        const float c1  = C[2 * idx + 1];

        const float are = __expf(arl);               // exp(log_A_real)
        const float dre = -dt * are;                 // Re(dtA)
        const float dim =  dt * aim;                 // Im(dtA)

        // w1 = exp(dtA); C_scaled = 2 * C * (w1 - 1) / A, A = (-are, aim)
        const float e1 = __expf(dre);
        float s1, co1; __sincosf(dim, &s1, &co1);
        const float numr = __fmaf_rn(e1, co1, -1.0f);
        const float numi = e1 * s1;
        const float tr = c0 * numr - c1 * numi;
        const float ti = c0 * numi + c1 * numr;
        const float inv = 2.0f / (are * are + aim * aim);
        const float csr = (ti * aim - tr * are) * inv;
        const float csi = -(ti * are + tr * aim) * inv;

        // step multiplier w = exp(LSTEP * dtA); |dim*LSTEP| <= ~160 rad
        const float m16 = __expf(dre * (float)LSTEP);
        const float p16 = red2pi_f(dim * (float)LSTEP);
        float s16, c16; __sincosf(p16, &s16, &c16);
        const float wr = m16 * c16;
        const float wi = m16 * s16;

        const float b = __fmaf_rn(wr, wr, wi * wi);  // |w|^2

        // base phase for this segment (the ONE fp64 reduction)
        const float pb = red2pi((double)dim * (double)l_base);

        stA[n] = make_float4(csr, csi, dre, dim);
        stB[n] = make_float4(pb, wr, wi, 1.0f / b);
        stC[n] = make_float2(2.0f * wr, -b);
    }
    __syncwarp();

    // ---------- Phase B: per-thread state + constants from staging ----------
    u64 xc[NPAIR], xo[NPAIR];        // x(l0), x(l0 - LSTEP)
    u64 au[NPAIR], nbu[NPAIR];       // a, -b   (register-resident constants)
    const float lhf = (float)lhalf;
    const float l0f = (float)l0;

    #pragma unroll
    for (int p = 0; p < NPAIR; ++p) {
        float xcv[2], xov[2], av[2], nbv[2];
        #pragma unroll
        for (int k = 0; k < 2; ++k) {
            const int n = half * 16 + 2 * p + k;
            const float4 A4 = stA[n];
            const float4 B4 = stB[n];
            const float2 C2 = stC[n];

            const float mag = __expf(A4.z * l0f);
            const float ph  = red2pi_f(__fmaf_rn(A4.w, lhf, B4.x));
            float sp, cp; __sincosf(ph, &sp, &cp);
            const float er = mag * cp, ei = mag * sp;
            const float y0r = A4.x * er - A4.y * ei;
            const float y0i = A4.x * ei + A4.y * er;

            xcv[k] = y0r;
            // x(l0 - LSTEP) = Re(y0 * conj(w)) / |w|^2
            xov[k] = __fmaf_rn(y0r, B4.y, y0i * B4.z) * B4.w;
            av[k]  = C2.x;
            nbv[k] = C2.y;
        }
        F2PACK(xc[p],  xcv[0], xcv[1]);
        F2PACK(xo[p],  xov[0], xov[1]);
        F2PACK(au[p],  av[0],  av[1]);
        F2PACK(nbu[p], nbv[0], nbv[1]);
    }

    float* out = K + (size_t)h * L + l_base + lhalf;

    // iters is even (128): ping-pong the two buffers, no register copies.
    #pragma unroll 1
    for (int it = 0; it < iters; it += 2) {
        BODY(xc, xo);   // outputs x(l), xo <- x(l+LSTEP)
        BODY(xo, xc);   // outputs x(l+LSTEP), xc <- x(l+2*LSTEP)
    }
}

extern "C" void kernel_launch(void* const* d_in, const int* in_sizes, int n_in,
                              void* d_out, int out_size) {
    const float* C          = (const float*)d_in[0];
    const float* log_dt     = (const float*)d_in[1];
    const float* log_A_real = (const float*)d_in[2];
    const float* A_imag     = (const float*)d_in[3];

    const int H = in_sizes[1];           // log_dt has H elements
    const int L = out_size / H;          // K is (H, L)
    const int iters = L / (SEGS * LSTEP);

    s4d_kernel<<<H * SEGS, 32>>>(C, log_dt, log_A_real, A_imag,
                                 (float*)d_out, H, L, iters);
}